// round 13
// baseline (speedup 1.0000x reference)
#include <cuda_runtime.h>
#include <cuda_bf16.h>
#include <cstdint>

// Shapes (fixed by the problem):
//   x:     [4, 256, 64, 64]
//   h:     [4, 128, 64, 64]   (half-res; h_up = 2x nearest upsample of h)
//   wgt:   [4, 200, 64, 64]   (kernel-gen branch at HALF res: constant over 2x2)
//   out:   [4, 128, 128, 128]
#define B_     4
#define CIN    256
#define COUT   128
#define HHALF  64
#define PHALF  4096        // 64*64
#define CRED   32
#define GROUPS 8
#define GC_    16
#define KK     25          // 5x5
#define SPAN   200         // KK*GROUPS

// Scratch (device globals; allocation inside kernel_launch is forbidden)
__device__ float g_h  [(size_t)B_ * COUT * PHALF];   // 8.4 MB
__device__ float g_wgt[(size_t)B_ * SPAN * PHALF];   // 13.1 MB
__device__ __nv_bfloat16 g_wh[COUT * CIN];           // w bf16 hi (o-major, k-contig)
__device__ __nv_bfloat16 g_wl[COUT * CIN];           // w bf16 lo residual
__device__ __nv_bfloat16 g_xh[(size_t)B_ * CIN * PHALF];  // x bf16 hi, [b][c][p]
__device__ __nv_bfloat16 g_xl[(size_t)B_ * CIN * PHALF];  // x bf16 lo residual

// ---- packed f32x2 helpers (per-lane identical to fmaf) ---------------------
__device__ __forceinline__ unsigned long long pk2(float a, float b) {
    unsigned long long r;
    asm("mov.b64 %0, {%1, %2};" : "=l"(r) : "f"(a), "f"(b));
    return r;
}
__device__ __forceinline__ void fma2(unsigned long long& d,
                                     unsigned long long a, unsigned long long b) {
    asm("fma.rn.f32x2 %0, %1, %2, %0;" : "+l"(d) : "l"(a), "l"(b));
}
__device__ __forceinline__ void upk2(unsigned long long v, float& lo, float& hi) {
    asm("mov.b64 {%0, %1}, %2;" : "=f"(lo), "=f"(hi) : "l"(v));
}

__device__ __forceinline__ uint32_t smem_u32(const void* p) {
    uint32_t a;
    asm("{ .reg .u64 t; cvta.to.shared.u64 t, %1; cvt.u32.u64 %0, t; }" : "=r"(a) : "l"(p));
    return a;
}
__device__ __forceinline__ void ldmx4(uint32_t* r, uint32_t addr) {
    asm volatile("ldmatrix.sync.aligned.m8n8.x4.shared.b16 {%0,%1,%2,%3}, [%4];"
                 : "=r"(r[0]), "=r"(r[1]), "=r"(r[2]), "=r"(r[3]) : "r"(addr));
}
__device__ __forceinline__ void ldmx2t(uint32_t* r, uint32_t addr) {
    asm volatile("ldmatrix.sync.aligned.m8n8.x2.trans.shared.b16 {%0,%1}, [%2];"
                 : "=r"(r[0]), "=r"(r[1]) : "r"(addr));
}
__device__ __forceinline__ void mma_bf16(float* d, const uint32_t* a, const uint32_t* b) {
    asm volatile(
        "mma.sync.aligned.m16n8k16.row.col.f32.bf16.bf16.f32 "
        "{%0,%1,%2,%3}, {%4,%5,%6,%7}, {%8,%9}, {%0,%1,%2,%3};"
        : "+f"(d[0]), "+f"(d[1]), "+f"(d[2]), "+f"(d[3])
        : "r"(a[0]), "r"(a[1]), "r"(a[2]), "r"(a[3]), "r"(b[0]), "r"(b[1]));
}

// ---------------------------------------------------------------------------
// convw_k: w1x1 fp32 [128][256] -> bf16 hi/lo split (o-major, k-contig)
// ---------------------------------------------------------------------------
__global__ __launch_bounds__(256) void convw_k(const float* __restrict__ w) {
    int i4 = blockIdx.x * 256 + threadIdx.x;           // 8192 quads
    float4 v = *(const float4*)(w + 4 * i4);
    float f[4] = {v.x, v.y, v.z, v.w};
    __nv_bfloat16 hi[4], lo[4];
#pragma unroll
    for (int j = 0; j < 4; j++) {
        hi[j] = __float2bfloat16(f[j]);
        lo[j] = __float2bfloat16(f[j] - __bfloat162float(hi[j]));
    }
    __nv_bfloat162* dh = (__nv_bfloat162*)(g_wh + 4 * i4);
    __nv_bfloat162* dl = (__nv_bfloat162*)(g_wl + 4 * i4);
    dh[0] = __halves2bfloat162(hi[0], hi[1]);
    dh[1] = __halves2bfloat162(hi[2], hi[3]);
    dl[0] = __halves2bfloat162(lo[0], lo[1]);
    dl[1] = __halves2bfloat162(lo[2], lo[3]);
}

// ---------------------------------------------------------------------------
// convx_k: ONE-PASS x fp32 -> bf16 hi/lo split, same [b][c][p] layout.
// Removes the duplicated in-GEMM conversion (was conv1's dominant cost).
// 4.19M elements, 4 per thread, fully coalesced.
// ---------------------------------------------------------------------------
__global__ __launch_bounds__(256) void convx_k(const float* __restrict__ x) {
    int i4 = blockIdx.x * 256 + threadIdx.x;           // 1,048,576 quads
    float4 v = *(const float4*)(x + 4 * (size_t)i4);
    float f[4] = {v.x, v.y, v.z, v.w};
    __nv_bfloat16 hi[4], lo[4];
#pragma unroll
    for (int j = 0; j < 4; j++) {
        hi[j] = __float2bfloat16(f[j]);
        lo[j] = __float2bfloat16(f[j] - __bfloat162float(hi[j]));
    }
    __nv_bfloat162* dh = (__nv_bfloat162*)(g_xh + 4 * (size_t)i4);
    __nv_bfloat162* dl = (__nv_bfloat162*)(g_xl + 4 * (size_t)i4);
    dh[0] = __halves2bfloat162(hi[0], hi[1]);
    dh[1] = __halves2bfloat162(hi[2], hi[3]);
    dl[0] = __halves2bfloat162(lo[0], lo[1]);
    dl[1] = __halves2bfloat162(lo[2], lo[3]);
}

// ---------------------------------------------------------------------------
// conv1_mma_k (v3): h = conv1x1 via warp-level bf16 mma.sync, fp32 accum.
//    D = Ah*Bh + Ah*Bl + Al*Bh   (Al*Bl dropped, ~2^-18 relative)
// CTA tile 64o x 64px, grid 512, smem 86 KB -> 2 CTAs/SM.
// B loader is now a PURE uint4 copy of pre-converted bf16 (no in-kernel cvt).
// ---------------------------------------------------------------------------
static constexpr int SA_H   = 0;                 // 64 rows * 528 B
static constexpr int SA_L   = 33792;
static constexpr int SB0    = 67584;             // 4 * (32 rows * 144 B)
static constexpr int SB_SZ  = 4608;
static constexpr int SM_TOT = 67584 + 4 * SB_SZ; // 86016 B

__global__ __launch_bounds__(256) void conv1_mma_k(const float* __restrict__ bias) {
    extern __shared__ char smem[];
    const uint32_t sbase = smem_u32(smem);
    const int tid  = threadIdx.x;
    const int wrp  = tid >> 5;
    const int lane = tid & 31;
    const int b      = blockIdx.z;
    const int o_base = blockIdx.y * 64;
    const int p0     = blockIdx.x * 64;

    const int wm = (wrp & 1) * 32;         // warp M offset (o)
    const int wn = (wrp >> 1) * 16;        // warp N offset (px)

    // ---- load A (w hi/lo rows o_base..o_base+63): 2048 uint4 each ----
    {
        const uint4* sh = (const uint4*)(g_wh + o_base * CIN);
        const uint4* sl = (const uint4*)(g_wl + o_base * CIN);
        for (int u = tid; u < 2048; u += 256) {
            int row = u >> 5, c16 = u & 31;
            *(uint4*)(smem + SA_H + row * 528 + c16 * 16) = sh[u];
            *(uint4*)(smem + SA_L + row * 528 + c16 * 16) = sl[u];
        }
    }

    // B source: bf16 [c][p], CTA's 64-px slice = 8 uint4 per k-row
    const __nv_bfloat16* xh = g_xh + (size_t)b * CIN * PHALF + p0;
    const __nv_bfloat16* xl = g_xl + (size_t)b * CIN * PHALF + p0;

    // ---- prefetch chunk 0: thread -> (row = tid>>3, c16 = tid&7), 256 uint4 each
    const int brow_ld = tid >> 3, bc16 = tid & 7;
    uint4 xrh, xrl;
    {
        xrh = ((const uint4*)(xh + (size_t)brow_ld * PHALF))[bc16];
        xrl = ((const uint4*)(xl + (size_t)brow_ld * PHALF))[bc16];
    }

    float acc[2][2][4];                    // [mt][nt][frag]
#pragma unroll
    for (int i = 0; i < 2; i++)
#pragma unroll
        for (int j = 0; j < 2; j++)
#pragma unroll
            for (int q = 0; q < 4; q++) acc[i][j][q] = 0.f;

    for (int kc = 0; kc < 8; kc++) {
        const int buf = kc & 1;
        const uint32_t bh_base = sbase + SB0 + (buf * 2 + 0) * SB_SZ;
        const uint32_t bl_base = sbase + SB0 + (buf * 2 + 1) * SB_SZ;

        // commit prefetched chunk (pure copies)
        *(uint4*)(smem + SB0 + (buf * 2 + 0) * SB_SZ + brow_ld * 144 + bc16 * 16) = xrh;
        *(uint4*)(smem + SB0 + (buf * 2 + 1) * SB_SZ + brow_ld * 144 + bc16 * 16) = xrl;
        __syncthreads();

        // prefetch next chunk (overlaps mma)
        if (kc < 7) {
            size_t roff = (size_t)((kc + 1) * 32 + brow_ld) * PHALF;
            xrh = ((const uint4*)(xh + roff))[bc16];
            xrl = ((const uint4*)(xl + roff))[bc16];
        }

        // ---- mma over this chunk: 2 ksteps of 16 ----
#pragma unroll
        for (int s = 0; s < 2; s++) {
            uint32_t a_h[2][4], a_l[2][4];
            const uint32_t akoff = (uint32_t)(kc * 64 + s * 32 + (lane >> 4) * 16);
#pragma unroll
            for (int mt = 0; mt < 2; mt++) {
                uint32_t arow = (uint32_t)(wm + mt * 16 + (lane & 15));
                ldmx4(a_h[mt], sbase + SA_H + arow * 528 + akoff);
                ldmx4(a_l[mt], sbase + SA_L + arow * 528 + akoff);
            }
            uint32_t b_h[2][2], b_l[2][2];
            const uint32_t brow = (uint32_t)(s * 16 + (lane & 15));
#pragma unroll
            for (int nt = 0; nt < 2; nt++) {
                uint32_t bcol = (uint32_t)((wn + nt * 8) * 2);
                ldmx2t(b_h[nt], bh_base + brow * 144 + bcol);
                ldmx2t(b_l[nt], bl_base + brow * 144 + bcol);
            }
#pragma unroll
            for (int mt = 0; mt < 2; mt++)
#pragma unroll
                for (int nt = 0; nt < 2; nt++) {
                    mma_bf16(acc[mt][nt], a_h[mt], b_h[nt]);
                    mma_bf16(acc[mt][nt], a_h[mt], b_l[nt]);
                    mma_bf16(acc[mt][nt], a_l[mt], b_h[nt]);
                }
        }
    }

    // ---- epilogue: bias + store ----
#pragma unroll
    for (int mt = 0; mt < 2; mt++) {
        int o0 = o_base + wm + mt * 16 + (lane >> 2);
        float bv0 = bias[o0];
        float bv1 = bias[o0 + 8];
#pragma unroll
        for (int nt = 0; nt < 2; nt++) {
            int px = p0 + wn + nt * 8 + (lane & 3) * 2;
            float* d0 = g_h + ((size_t)b * COUT + o0) * PHALF + px;
            float* d1 = g_h + ((size_t)b * COUT + o0 + 8) * PHALF + px;
            *(float2*)d0 = make_float2(acc[mt][nt][0] + bv0, acc[mt][nt][1] + bv0);
            *(float2*)d1 = make_float2(acc[mt][nt][2] + bv1, acc[mt][nt][3] + bv1);
        }
    }
}

// ---------------------------------------------------------------------------
// Kernel 2: kernel-generation branch AT HALF RES (unchanged).
// ---------------------------------------------------------------------------
__global__ __launch_bounds__(256) void kgen_k(const float* __restrict__ wred,
                                              const float* __restrict__ bred,
                                              const float* __restrict__ gamma,
                                              const float* __restrict__ beta,
                                              const float* __restrict__ mean,
                                              const float* __restrict__ var,
                                              const float* __restrict__ wspan,
                                              const float* __restrict__ bspan) {
    __shared__ float pool[6600];
    __shared__ float h_sh[16][64];
    __shared__ float r_sh[CRED][68];

    const int tid = threadIdx.x;
    const int q0  = blockIdx.x * 64;
    const int b   = q0 >> 12;
    const int p0  = q0 & 4095;

    for (int i = tid; i < CRED * COUT; i += 256) {
        int o = i >> 7, c = i & 127;
        pool[c * CRED + o] = wred[i];
    }

    const int oq  = tid >> 5;
    const int pxp = tid & 31;

    float acc[4][2];
#pragma unroll
    for (int i = 0; i < 4; i++) {
        float bv = bred[4 * oq + i];
        acc[i][0] = bv; acc[i][1] = bv;
    }

    const float* hb = g_h + (size_t)b * COUT * PHALF + p0;
    const int hc = tid >> 4, hp4 = tid & 15;

    for (int cc = 0; cc < COUT; cc += 16) {
        __syncthreads();
        *(float4*)&h_sh[hc][4 * hp4] =
            *(const float4*)(hb + (size_t)(cc + hc) * PHALF + 4 * hp4);
        __syncthreads();
#pragma unroll
        for (int c = 0; c < 16; c++) {
            float4 wv = *(const float4*)&pool[(cc + c) * CRED + 4 * oq];
            float2 hv = *(const float2*)&h_sh[c][2 * pxp];
            acc[0][0] += wv.x * hv.x;  acc[0][1] += wv.x * hv.y;
            acc[1][0] += wv.y * hv.x;  acc[1][1] += wv.y * hv.y;
            acc[2][0] += wv.z * hv.x;  acc[2][1] += wv.z * hv.y;
            acc[3][0] += wv.w * hv.x;  acc[3][1] += wv.w * hv.y;
        }
    }

#pragma unroll
    for (int i = 0; i < 4; i++) {
        int o = 4 * oq + i;
        float sc = gamma[o] * rsqrtf(var[o] + 1e-5f);
        float sh = beta[o] - mean[o] * sc;
        float v0 = fmaxf(acc[i][0] * sc + sh, 0.f);
        float v1 = fmaxf(acc[i][1] * sc + sh, 0.f);
        *(float2*)&r_sh[o][2 * pxp] = make_float2(v0, v1);
    }
    __syncthreads();

    for (int i = tid; i < SPAN * CRED; i += 256) {
        int s = i >> 5, oo = i & 31;
        pool[s * 33 + oo] = wspan[i];
    }
    __syncthreads();

    if (tid < 200) {
        const int s0 = (tid >> 3) * 8;
        const int px = (tid & 7) * 8;

        float acc2[8][8];
#pragma unroll
        for (int i = 0; i < 8; i++) {
            float bv = bspan[s0 + i];
#pragma unroll
            for (int j = 0; j < 8; j++) acc2[i][j] = bv;
        }

#pragma unroll 4
        for (int oo = 0; oo < CRED; oo++) {
            float w8[8];
#pragma unroll
            for (int i = 0; i < 8; i++) w8[i] = pool[(s0 + i) * 33 + oo];
            float4 ra = *(const float4*)&r_sh[oo][px];
            float4 rb = *(const float4*)&r_sh[oo][px + 4];
#pragma unroll
            for (int i = 0; i < 8; i++) {
                acc2[i][0] += w8[i] * ra.x;  acc2[i][1] += w8[i] * ra.y;
                acc2[i][2] += w8[i] * ra.z;  acc2[i][3] += w8[i] * ra.w;
                acc2[i][4] += w8[i] * rb.x;  acc2[i][5] += w8[i] * rb.y;
                acc2[i][6] += w8[i] * rb.z;  acc2[i][7] += w8[i] * rb.w;
            }
        }

        float* wb = g_wgt + (size_t)b * SPAN * PHALF + p0 + px;
#pragma unroll
        for (int i = 0; i < 8; i++) {
            float4 v0 = make_float4(acc2[i][0], acc2[i][1], acc2[i][2], acc2[i][3]);
            float4 v1 = make_float4(acc2[i][4], acc2[i][5], acc2[i][6], acc2[i][7]);
            *(float4*)(wb + (size_t)(s0 + i) * PHALF)     = v0;
            *(float4*)(wb + (size_t)(s0 + i) * PHALF + 4) = v1;
        }
    }
}

// ---------------------------------------------------------------------------
// Kernel 3: involution, pre-collapsed 3x3 weights, 16 channels/block (R11).
// ---------------------------------------------------------------------------
__global__ __launch_bounds__(256) void inv_k(float* __restrict__ out) {
    __shared__ float2 hs[GC_][18][19];   // duplicated halo'd h tile, ~43.8 KB

    const int b = blockIdx.z;
    const int g = blockIdx.y;
    const int ti = (blockIdx.x >> 2) * 16;
    const int tj = (blockIdx.x & 3) * 16;
    const int tid = threadIdx.x;

    const float* hb = g_h + ((size_t)b * COUT + g * GC_) * PHALF;
    for (int e = tid; e < GC_ * 324; e += 256) {
        int c   = e / 324;
        int rem = e - c * 324;
        int rr  = rem / 18, cc = rem - rr * 18;
        int gi = ti - 1 + rr, gj = tj - 1 + cc;
        float v = 0.f;
        if ((unsigned)gi < 64u && (unsigned)gj < 64u)
            v = hb[(size_t)c * PHALF + gi * HHALF + gj];
        hs[c][rr][cc] = make_float2(v, v);
    }

    const int jl = tid & 15, il = tid >> 4;
    const int pix = (ti + il) * HHALF + (tj + jl);

    // ---- load 25 weights, collapse to 4 effective 3x3 kernels, pack ----
    unsigned long long wA[9], wB[9];     // (W00,W01) and (W10,W11)
    {
        float wk[KK];
        const float* wgp = g_wgt + ((size_t)b * SPAN + g * KK) * PHALF + pix;
#pragma unroll
        for (int k = 0; k < KK; k++) wk[k] = wgp[(size_t)k * PHALF];

        float P0[3][5], P1[3][5];
#pragma unroll
        for (int kw = 0; kw < 5; kw++) {
            P0[0][kw] = wk[0 + kw] + wk[5 + kw];
            P0[1][kw] = wk[10 + kw] + wk[15 + kw];
            P0[2][kw] = wk[20 + kw];
            P1[0][kw] = wk[0 + kw];
            P1[1][kw] = wk[5 + kw] + wk[10 + kw];
            P1[2][kw] = wk[15 + kw] + wk[20 + kw];
        }
#pragma unroll
        for (int r = 0; r < 3; r++) {
            wA[r * 3 + 0] = pk2(P0[r][0] + P0[r][1], P0[r][0]);
            wA[r * 3 + 1] = pk2(P0[r][2] + P0[r][3], P0[r][1] + P0[r][2]);
            wA[r * 3 + 2] = pk2(P0[r][4],            P0[r][3] + P0[r][4]);
            wB[r * 3 + 0] = pk2(P1[r][0] + P1[r][1], P1[r][0]);
            wB[r * 3 + 1] = pk2(P1[r][2] + P1[r][3], P1[r][1] + P1[r][2]);
            wB[r * 3 + 2] = pk2(P1[r][4],            P1[r][3] + P1[r][4]);
        }
    }

    __syncthreads();

    const int y0 = 2 * (ti + il), x0 = 2 * (tj + jl);
    float* ob = out + (((size_t)b * COUT + g * GC_) * 128 + y0) * 128 + x0;

#pragma unroll
    for (int c = 0; c < GC_; c++) {
        unsigned long long m[9];
#pragma unroll
        for (int a = 0; a < 3; a++)
#pragma unroll
            for (int d = 0; d < 3; d++)
                m[a * 3 + d] = *(const unsigned long long*)&hs[c][il + a][jl + d];

        unsigned long long accA = 0ull;  // (a00, a01)
        unsigned long long accB = 0ull;  // (a10, a11)
#pragma unroll
        for (int i = 0; i < 9; i++) {
            fma2(accA, wA[i], m[i]);
            fma2(accB, wB[i], m[i]);
        }
        float a00, a01, a10, a11;
        upk2(accA, a00, a01);
        upk2(accB, a10, a11);
        *reinterpret_cast<float2*>(ob + (size_t)c * 16384)       = make_float2(a00, a01);
        *reinterpret_cast<float2*>(ob + (size_t)c * 16384 + 128) = make_float2(a10, a11);
    }
}

// ---------------------------------------------------------------------------
extern "C" void kernel_launch(void* const* d_in, const int* in_sizes, int n_in,
                              void* d_out, int out_size) {
    const float* x      = (const float*)d_in[0];
    const float* w1x1   = (const float*)d_in[1];
    const float* b1x1   = (const float*)d_in[2];
    const float* w_red  = (const float*)d_in[3];
    const float* b_red  = (const float*)d_in[4];
    const float* gamma  = (const float*)d_in[5];
    const float* beta   = (const float*)d_in[6];
    const float* mean   = (const float*)d_in[7];
    const float* var    = (const float*)d_in[8];
    const float* w_span = (const float*)d_in[9];
    const float* b_span = (const float*)d_in[10];
    float* out = (float*)d_out;

    cudaFuncSetAttribute(conv1_mma_k,
                         cudaFuncAttributeMaxDynamicSharedMemorySize, SM_TOT);

    convw_k<<<32, 256>>>(w1x1);
    convx_k<<<4096, 256>>>(x);
    conv1_mma_k<<<dim3(PHALF / 64, 2, B_), 256, SM_TOT>>>(b1x1);
    kgen_k<<<dim3((B_ * PHALF) / 64, 1, 1), 256>>>(w_red, b_red, gamma, beta,
                                                   mean, var, w_span, b_span);
    inv_k<<<dim3(16, GROUPS, B_), 256>>>(out);
}

// round 15
// speedup vs baseline: 1.0537x; 1.0537x over previous
#include <cuda_runtime.h>
#include <cuda_bf16.h>
#include <cstdint>

// Shapes (fixed by the problem):
//   x:     [4, 256, 64, 64]
//   h:     [4, 128, 64, 64]   (half-res; h_up = 2x nearest upsample of h)
//   wgt:   [4, 200, 64, 64]   (kernel-gen branch at HALF res: constant over 2x2)
//   out:   [4, 128, 128, 128]
#define B_     4
#define CIN    256
#define COUT   128
#define HHALF  64
#define PHALF  4096        // 64*64
#define CRED   32
#define GROUPS 8
#define GC_    16
#define KK     25          // 5x5
#define SPAN   200         // KK*GROUPS

// Scratch (device globals; allocation inside kernel_launch is forbidden)
__device__ float g_h  [(size_t)B_ * COUT * PHALF];   // 8.4 MB
__device__ float g_wgt[(size_t)B_ * SPAN * PHALF];   // 13.1 MB
__device__ __nv_bfloat16 g_wh[COUT * CIN];           // w bf16 hi (o-major, k-contig)
__device__ __nv_bfloat16 g_wl[COUT * CIN];           // w bf16 lo residual

// ---- packed f32x2 helpers (per-lane identical to fmaf) ---------------------
__device__ __forceinline__ unsigned long long pk2(float a, float b) {
    unsigned long long r;
    asm("mov.b64 %0, {%1, %2};" : "=l"(r) : "f"(a), "f"(b));
    return r;
}
__device__ __forceinline__ void fma2(unsigned long long& d,
                                     unsigned long long a, unsigned long long b) {
    asm("fma.rn.f32x2 %0, %1, %2, %0;" : "+l"(d) : "l"(a), "l"(b));
}
__device__ __forceinline__ void upk2(unsigned long long v, float& lo, float& hi) {
    asm("mov.b64 {%0, %1}, %2;" : "=f"(lo), "=f"(hi) : "l"(v));
}

__device__ __forceinline__ uint32_t smem_u32(const void* p) {
    uint32_t a;
    asm("{ .reg .u64 t; cvta.to.shared.u64 t, %1; cvt.u32.u64 %0, t; }" : "=r"(a) : "l"(p));
    return a;
}
__device__ __forceinline__ void ldmx4(uint32_t* r, uint32_t addr) {
    asm volatile("ldmatrix.sync.aligned.m8n8.x4.shared.b16 {%0,%1,%2,%3}, [%4];"
                 : "=r"(r[0]), "=r"(r[1]), "=r"(r[2]), "=r"(r[3]) : "r"(addr));
}
__device__ __forceinline__ void ldmx2t(uint32_t* r, uint32_t addr) {
    asm volatile("ldmatrix.sync.aligned.m8n8.x2.trans.shared.b16 {%0,%1}, [%2];"
                 : "=r"(r[0]), "=r"(r[1]) : "r"(addr));
}
__device__ __forceinline__ void mma_bf16(float* d, const uint32_t* a, const uint32_t* b) {
    asm volatile(
        "mma.sync.aligned.m16n8k16.row.col.f32.bf16.bf16.f32 "
        "{%0,%1,%2,%3}, {%4,%5,%6,%7}, {%8,%9}, {%0,%1,%2,%3};"
        : "+f"(d[0]), "+f"(d[1]), "+f"(d[2]), "+f"(d[3])
        : "r"(a[0]), "r"(a[1]), "r"(a[2]), "r"(a[3]), "r"(b[0]), "r"(b[1]));
}

// ---------------------------------------------------------------------------
// convw_k: w1x1 fp32 [128][256] -> bf16 hi/lo split (o-major, k-contig)
// ---------------------------------------------------------------------------
__global__ __launch_bounds__(256) void convw_k(const float* __restrict__ w) {
    int i4 = blockIdx.x * 256 + threadIdx.x;           // 8192 quads
    float4 v = *(const float4*)(w + 4 * i4);
    float f[4] = {v.x, v.y, v.z, v.w};
    __nv_bfloat16 hi[4], lo[4];
#pragma unroll
    for (int j = 0; j < 4; j++) {
        hi[j] = __float2bfloat16(f[j]);
        lo[j] = __float2bfloat16(f[j] - __bfloat162float(hi[j]));
    }
    __nv_bfloat162* dh = (__nv_bfloat162*)(g_wh + 4 * i4);
    __nv_bfloat162* dl = (__nv_bfloat162*)(g_wl + 4 * i4);
    dh[0] = __halves2bfloat162(hi[0], hi[1]);
    dh[1] = __halves2bfloat162(hi[2], hi[3]);
    dl[0] = __halves2bfloat162(lo[0], lo[1]);
    dl[1] = __halves2bfloat162(lo[2], lo[3]);
}

// ---------------------------------------------------------------------------
// conv1_mma_k (R11 config — HMMA-throughput-bound, best measured ~24us path):
// D[o=128][px=128] per CTA, K=256 fp32 split into bf16 (hi,lo):
//    D = Ah*Bh + Ah*Bl + Al*Bh   (Al*Bl dropped, ~2^-18 relative)
// A = w hi/lo smem-resident (row pad 528B); B = x chunk converted in-kernel,
// [k][px] rows pad 272B, ldmatrix.x2.trans. 8 warps, warp tile 64M x 32N.
// ---------------------------------------------------------------------------
static constexpr int SA_H   = 0;            // 128 rows * 528 B
static constexpr int SA_L   = 67584;
static constexpr int SB     = 135168;       // 4 * (32 rows * 272 B) : [buf][hl]
static constexpr int SB_SZ  = 8704;
static constexpr int SM_TOT = 135168 + 4 * SB_SZ;   // 169984 B

__global__ __launch_bounds__(256) void conv1_mma_k(const float* __restrict__ x,
                                                   const float* __restrict__ bias) {
    extern __shared__ char smem[];
    const uint32_t sbase = smem_u32(smem);
    const int tid  = threadIdx.x;
    const int wrp  = tid >> 5;
    const int lane = tid & 31;
    const int b    = blockIdx.y;
    const int p0   = blockIdx.x * 128;

    const int wm = (wrp & 1) * 64;         // warp M offset (o)
    const int wn = (wrp >> 1) * 32;        // warp N offset (px)

    // ---- load A (w hi/lo) into smem once: 4096 uint4 each ----
    {
        const uint4* sh = (const uint4*)g_wh;
        const uint4* sl = (const uint4*)g_wl;
        for (int u = tid; u < 4096; u += 256) {
            int row = u >> 5, c16 = u & 31;
            *(uint4*)(smem + SA_H + row * 528 + c16 * 16) = sh[u];
            *(uint4*)(smem + SA_L + row * 528 + c16 * 16) = sl[u];
        }
    }

    // ---- B prefetch chunk 0 (32 k-rows x 128 px fp32) ----
    const float* xb = x + (size_t)b * CIN * PHALF + p0;
    float4 xr[4];
#pragma unroll
    for (int i = 0; i < 4; i++) {
        int u = tid + i * 256;
        int row = u >> 5, seg = u & 31;
        xr[i] = ((const float4*)(xb + (size_t)row * PHALF))[seg];
    }

    float acc[4][4][4];                    // [mt][nt][frag]
#pragma unroll
    for (int i = 0; i < 4; i++)
#pragma unroll
        for (int j = 0; j < 4; j++)
#pragma unroll
            for (int q = 0; q < 4; q++) acc[i][j][q] = 0.f;

    for (int kc = 0; kc < 8; kc++) {
        const int buf = kc & 1;
        const uint32_t bh_base = sbase + SB + (buf * 2 + 0) * SB_SZ;
        const uint32_t bl_base = sbase + SB + (buf * 2 + 1) * SB_SZ;

        // convert + store prefetched chunk into smem (hi & lo)
#pragma unroll
        for (int i = 0; i < 4; i++) {
            int u = tid + i * 256;
            int row = u >> 5, seg = u & 31;
            float f[4] = {xr[i].x, xr[i].y, xr[i].z, xr[i].w};
            __nv_bfloat16 hi[4], lo[4];
#pragma unroll
            for (int j = 0; j < 4; j++) {
                hi[j] = __float2bfloat16(f[j]);
                lo[j] = __float2bfloat16(f[j] - __bfloat162float(hi[j]));
            }
            char* ph = smem + SB + (buf * 2 + 0) * SB_SZ + row * 272 + seg * 8;
            char* pl = smem + SB + (buf * 2 + 1) * SB_SZ + row * 272 + seg * 8;
            ((__nv_bfloat162*)ph)[0] = __halves2bfloat162(hi[0], hi[1]);
            ((__nv_bfloat162*)ph)[1] = __halves2bfloat162(hi[2], hi[3]);
            ((__nv_bfloat162*)pl)[0] = __halves2bfloat162(lo[0], lo[1]);
            ((__nv_bfloat162*)pl)[1] = __halves2bfloat162(lo[2], lo[3]);
        }
        __syncthreads();

        // prefetch next chunk (overlaps with mma below)
        if (kc < 7) {
#pragma unroll
            for (int i = 0; i < 4; i++) {
                int u = tid + i * 256;
                int row = u >> 5, seg = u & 31;
                xr[i] = ((const float4*)(xb + (size_t)((kc + 1) * 32 + row) * PHALF))[seg];
            }
        }

        // ---- mma over this chunk: 2 ksteps of 16 ----
#pragma unroll
        for (int s = 0; s < 2; s++) {
            uint32_t a_h[4][4], a_l[4][4];
            const uint32_t akoff = (uint32_t)(kc * 64 + s * 32 + (lane >> 4) * 16);
#pragma unroll
            for (int mt = 0; mt < 4; mt++) {
                uint32_t arow = (uint32_t)(wm + mt * 16 + (lane & 15));
                ldmx4(a_h[mt], sbase + SA_H + arow * 528 + akoff);
                ldmx4(a_l[mt], sbase + SA_L + arow * 528 + akoff);
            }
            uint32_t b_h[4][2], b_l[4][2];
            const uint32_t brow = (uint32_t)(s * 16 + (lane & 15));
#pragma unroll
            for (int nt = 0; nt < 4; nt++) {
                uint32_t bcol = (uint32_t)((wn + nt * 8) * 2);
                ldmx2t(b_h[nt], bh_base + brow * 272 + bcol);
                ldmx2t(b_l[nt], bl_base + brow * 272 + bcol);
            }
#pragma unroll
            for (int mt = 0; mt < 4; mt++)
#pragma unroll
                for (int nt = 0; nt < 4; nt++) {
                    mma_bf16(acc[mt][nt], a_h[mt], b_h[nt]);
                    mma_bf16(acc[mt][nt], a_h[mt], b_l[nt]);
                    mma_bf16(acc[mt][nt], a_l[mt], b_h[nt]);
                }
        }
        __syncthreads();
    }

    // ---- epilogue: bias + store ----
#pragma unroll
    for (int mt = 0; mt < 4; mt++) {
        int o0 = wm + mt * 16 + (lane >> 2);
        float bv0 = bias[o0];
        float bv1 = bias[o0 + 8];
#pragma unroll
        for (int nt = 0; nt < 4; nt++) {
            int px = p0 + wn + nt * 8 + (lane & 3) * 2;
            float* d0 = g_h + ((size_t)b * COUT + o0) * PHALF + px;
            float* d1 = g_h + ((size_t)b * COUT + o0 + 8) * PHALF + px;
            *(float2*)d0 = make_float2(acc[mt][nt][0] + bv0, acc[mt][nt][1] + bv0);
            *(float2*)d1 = make_float2(acc[mt][nt][2] + bv1, acc[mt][nt][3] + bv1);
        }
    }
}

// ---------------------------------------------------------------------------
// Kernel 2 (v3): kernel-generation branch, 32-px blocks -> grid 512.
//   Stage 1: r = relu(bn(w_red @ h)), thread = 4o (warp-uniform) x 1px.
//   Stage 2: wgt = w_span @ r, microtile 8s x 4px (32 acc regs, was 64).
// Occupancy target ~2x R13 (grid 256->512, regs ~112->~70).
// ---------------------------------------------------------------------------
__global__ __launch_bounds__(256) void kgen_k(const float* __restrict__ wred,
                                              const float* __restrict__ bred,
                                              const float* __restrict__ gamma,
                                              const float* __restrict__ beta,
                                              const float* __restrict__ mean,
                                              const float* __restrict__ var,
                                              const float* __restrict__ wspan,
                                              const float* __restrict__ bspan) {
    __shared__ float pool[6600];        // stage1: wredT[4096]; stage2: wspan [200][33]
    __shared__ float h_sh[16][32];      // h chunk (16 ch x 32 px)
    __shared__ float r_sh[CRED][36];    // [o][px], rows 144B (aligned float4)

    const int tid = threadIdx.x;
    const int q0  = blockIdx.x * 32;    // global half-pixel id (b*4096 + p)
    const int b   = q0 >> 12;
    const int p0  = q0 & 4095;

    // wred transposed: pool[c*32 + o] = wred[o*128 + c]
    for (int i = tid; i < CRED * COUT; i += 256) {
        int o = i >> 7, c = i & 127;
        pool[c * CRED + o] = wred[i];
    }

    // ---- stage 1: thread = (oq warp-uniform, lane px) -> 4 o x 1 px ----
    const int oq   = tid >> 5;         // 0..7, warp-uniform -> w reads broadcast
    const int lane = tid & 31;         // px

    float acc[4];
#pragma unroll
    for (int i = 0; i < 4; i++) acc[i] = bred[4 * oq + i];

    const float* hb = g_h + (size_t)b * COUT * PHALF + p0;
    const int hc = tid >> 4, hp2 = (tid & 15) * 2;   // h loader: one float2 each

    for (int cc = 0; cc < COUT; cc += 16) {
        __syncthreads();
        *(float2*)&h_sh[hc][hp2] =
            *(const float2*)(hb + (size_t)(cc + hc) * PHALF + hp2);
        __syncthreads();
#pragma unroll
        for (int c = 0; c < 16; c++) {
            float4 wv = *(const float4*)&pool[(cc + c) * CRED + 4 * oq];  // broadcast
            float hv = h_sh[c][lane];
            acc[0] += wv.x * hv;
            acc[1] += wv.y * hv;
            acc[2] += wv.z * hv;
            acc[3] += wv.w * hv;
        }
    }

    // BN + ReLU -> r_sh
#pragma unroll
    for (int i = 0; i < 4; i++) {
        int o = 4 * oq + i;
        float sc = gamma[o] * rsqrtf(var[o] + 1e-5f);
        float sh = beta[o] - mean[o] * sc;
        r_sh[o][lane] = fmaxf(acc[i] * sc + sh, 0.f);
    }
    __syncthreads();

    // ---- stage 2: wspan into pool with row pad 33 ----
    for (int i = tid; i < SPAN * CRED; i += 256) {
        int s = i >> 5, oo = i & 31;
        pool[s * 33 + oo] = wspan[i];
    }
    __syncthreads();

    // thread = (s-tile of 8, px-group of 4): 25 x 8 = 200 active threads.
    if (tid < 200) {
        const int s0 = (tid >> 3) * 8;     // 0,8,...,192
        const int px = (tid & 7) * 4;      // 0..28

        float acc2[8][4];
#pragma unroll
        for (int i = 0; i < 8; i++) {
            float bv = bspan[s0 + i];
#pragma unroll
            for (int j = 0; j < 4; j++) acc2[i][j] = bv;
        }

#pragma unroll 4
        for (int oo = 0; oo < CRED; oo++) {
            float w8[8];
#pragma unroll
            for (int i = 0; i < 8; i++) w8[i] = pool[(s0 + i) * 33 + oo];
            float4 ra = *(const float4*)&r_sh[oo][px];
#pragma unroll
            for (int i = 0; i < 8; i++) {
                acc2[i][0] += w8[i] * ra.x;  acc2[i][1] += w8[i] * ra.y;
                acc2[i][2] += w8[i] * ra.z;  acc2[i][3] += w8[i] * ra.w;
            }
        }

        float* wb = g_wgt + (size_t)b * SPAN * PHALF + p0 + px;
#pragma unroll
        for (int i = 0; i < 8; i++) {
            *(float4*)(wb + (size_t)(s0 + i) * PHALF) =
                make_float4(acc2[i][0], acc2[i][1], acc2[i][2], acc2[i][3]);
        }
    }
}

// ---------------------------------------------------------------------------
// Kernel 3: involution, pre-collapsed 3x3 weights, 16 channels/block (R11).
// ---------------------------------------------------------------------------
__global__ __launch_bounds__(256) void inv_k(float* __restrict__ out) {
    __shared__ float2 hs[GC_][18][19];   // duplicated halo'd h tile, ~43.8 KB

    const int b = blockIdx.z;
    const int g = blockIdx.y;
    const int ti = (blockIdx.x >> 2) * 16;
    const int tj = (blockIdx.x & 3) * 16;
    const int tid = threadIdx.x;

    const float* hb = g_h + ((size_t)b * COUT + g * GC_) * PHALF;
    for (int e = tid; e < GC_ * 324; e += 256) {
        int c   = e / 324;
        int rem = e - c * 324;
        int rr  = rem / 18, cc = rem - rr * 18;
        int gi = ti - 1 + rr, gj = tj - 1 + cc;
        float v = 0.f;
        if ((unsigned)gi < 64u && (unsigned)gj < 64u)
            v = hb[(size_t)c * PHALF + gi * HHALF + gj];
        hs[c][rr][cc] = make_float2(v, v);
    }

    const int jl = tid & 15, il = tid >> 4;
    const int pix = (ti + il) * HHALF + (tj + jl);

    // ---- load 25 weights, collapse to 4 effective 3x3 kernels, pack ----
    unsigned long long wA[9], wB[9];     // (W00,W01) and (W10,W11)
    {
        float wk[KK];
        const float* wgp = g_wgt + ((size_t)b * SPAN + g * KK) * PHALF + pix;
#pragma unroll
        for (int k = 0; k < KK; k++) wk[k] = wgp[(size_t)k * PHALF];

        float P0[3][5], P1[3][5];
#pragma unroll
        for (int kw = 0; kw < 5; kw++) {
            P0[0][kw] = wk[0 + kw] + wk[5 + kw];
            P0[1][kw] = wk[10 + kw] + wk[15 + kw];
            P0[2][kw] = wk[20 + kw];
            P1[0][kw] = wk[0 + kw];
            P1[1][kw] = wk[5 + kw] + wk[10 + kw];
            P1[2][kw] = wk[15 + kw] + wk[20 + kw];
        }
#pragma unroll
        for (int r = 0; r < 3; r++) {
            wA[r * 3 + 0] = pk2(P0[r][0] + P0[r][1], P0[r][0]);
            wA[r * 3 + 1] = pk2(P0[r][2] + P0[r][3], P0[r][1] + P0[r][2]);
            wA[r * 3 + 2] = pk2(P0[r][4],            P0[r][3] + P0[r][4]);
            wB[r * 3 + 0] = pk2(P1[r][0] + P1[r][1], P1[r][0]);
            wB[r * 3 + 1] = pk2(P1[r][2] + P1[r][3], P1[r][1] + P1[r][2]);
            wB[r * 3 + 2] = pk2(P1[r][4],            P1[r][3] + P1[r][4]);
        }
    }

    __syncthreads();

    const int y0 = 2 * (ti + il), x0 = 2 * (tj + jl);
    float* ob = out + (((size_t)b * COUT + g * GC_) * 128 + y0) * 128 + x0;

#pragma unroll
    for (int c = 0; c < GC_; c++) {
        unsigned long long m[9];
#pragma unroll
        for (int a = 0; a < 3; a++)
#pragma unroll
            for (int d = 0; d < 3; d++)
                m[a * 3 + d] = *(const unsigned long long*)&hs[c][il + a][jl + d];

        unsigned long long accA = 0ull;  // (a00, a01)
        unsigned long long accB = 0ull;  // (a10, a11)
#pragma unroll
        for (int i = 0; i < 9; i++) {
            fma2(accA, wA[i], m[i]);
            fma2(accB, wB[i], m[i]);
        }
        float a00, a01, a10, a11;
        upk2(accA, a00, a01);
        upk2(accB, a10, a11);
        *reinterpret_cast<float2*>(ob + (size_t)c * 16384)       = make_float2(a00, a01);
        *reinterpret_cast<float2*>(ob + (size_t)c * 16384 + 128) = make_float2(a10, a11);
    }
}

// ---------------------------------------------------------------------------
extern "C" void kernel_launch(void* const* d_in, const int* in_sizes, int n_in,
                              void* d_out, int out_size) {
    const float* x      = (const float*)d_in[0];
    const float* w1x1   = (const float*)d_in[1];
    const float* b1x1   = (const float*)d_in[2];
    const float* w_red  = (const float*)d_in[3];
    const float* b_red  = (const float*)d_in[4];
    const float* gamma  = (const float*)d_in[5];
    const float* beta   = (const float*)d_in[6];
    const float* mean   = (const float*)d_in[7];
    const float* var    = (const float*)d_in[8];
    const float* w_span = (const float*)d_in[9];
    const float* b_span = (const float*)d_in[10];
    float* out = (float*)d_out;

    cudaFuncSetAttribute(conv1_mma_k,
                         cudaFuncAttributeMaxDynamicSharedMemorySize, SM_TOT);

    convw_k<<<32, 256>>>(w1x1);
    conv1_mma_k<<<dim3(PHALF / 128, B_), 256, SM_TOT>>>(x, b1x1);
    kgen_k<<<dim3((B_ * PHALF) / 32, 1, 1), 256>>>(w_red, b_red, gamma, beta,
                                                   mean, var, w_span, b_span);
    inv_k<<<dim3(16, GROUPS, B_), 256>>>(out);
}

// round 17
// speedup vs baseline: 1.0877x; 1.0322x over previous
#include <cuda_runtime.h>
#include <cuda_bf16.h>
#include <cstdint>

// Shapes (fixed by the problem):
//   x:     [4, 256, 64, 64]
//   h:     [4, 128, 64, 64]   (half-res; h_up = 2x nearest upsample of h)
//   r:     [4, 32, 64, 64]    (reduction branch, half-res)
//   wgt:   [4, 200, 64, 64]   (involution weights at half-res)
//   out:   [4, 128, 128, 128]
#define B_     4
#define CIN    256
#define COUT   128
#define HHALF  64
#define PHALF  4096        // 64*64
#define CRED   32
#define GROUPS 8
#define GC_    16
#define KK     25          // 5x5
#define SPAN   200         // KK*GROUPS

// Scratch (device globals; allocation inside kernel_launch is forbidden)
__device__ float g_h  [(size_t)B_ * COUT * PHALF];   // 8.4 MB
__device__ float g_r  [(size_t)B_ * CRED * PHALF];   // 2.1 MB
__device__ float g_wgt[(size_t)B_ * SPAN * PHALF];   // 13.1 MB
__device__ __nv_bfloat16 g_wh[COUT * CIN];           // w bf16 hi (o-major, k-contig)
__device__ __nv_bfloat16 g_wl[COUT * CIN];           // w bf16 lo residual

// ---- packed f32x2 helpers (per-lane identical to fmaf) ---------------------
__device__ __forceinline__ unsigned long long pk2(float a, float b) {
    unsigned long long r;
    asm("mov.b64 %0, {%1, %2};" : "=l"(r) : "f"(a), "f"(b));
    return r;
}
__device__ __forceinline__ void fma2(unsigned long long& d,
                                     unsigned long long a, unsigned long long b) {
    asm("fma.rn.f32x2 %0, %1, %2, %0;" : "+l"(d) : "l"(a), "l"(b));
}
__device__ __forceinline__ void upk2(unsigned long long v, float& lo, float& hi) {
    asm("mov.b64 {%0, %1}, %2;" : "=f"(lo), "=f"(hi) : "l"(v));
}

__device__ __forceinline__ uint32_t smem_u32(const void* p) {
    uint32_t a;
    asm("{ .reg .u64 t; cvta.to.shared.u64 t, %1; cvt.u32.u64 %0, t; }" : "=r"(a) : "l"(p));
    return a;
}
__device__ __forceinline__ void ldmx4(uint32_t* r, uint32_t addr) {
    asm volatile("ldmatrix.sync.aligned.m8n8.x4.shared.b16 {%0,%1,%2,%3}, [%4];"
                 : "=r"(r[0]), "=r"(r[1]), "=r"(r[2]), "=r"(r[3]) : "r"(addr));
}
__device__ __forceinline__ void ldmx2t(uint32_t* r, uint32_t addr) {
    asm volatile("ldmatrix.sync.aligned.m8n8.x2.trans.shared.b16 {%0,%1}, [%2];"
                 : "=r"(r[0]), "=r"(r[1]) : "r"(addr));
}
__device__ __forceinline__ void mma_bf16(float* d, const uint32_t* a, const uint32_t* b) {
    asm volatile(
        "mma.sync.aligned.m16n8k16.row.col.f32.bf16.bf16.f32 "
        "{%0,%1,%2,%3}, {%4,%5,%6,%7}, {%8,%9}, {%0,%1,%2,%3};"
        : "+f"(d[0]), "+f"(d[1]), "+f"(d[2]), "+f"(d[3])
        : "r"(a[0]), "r"(a[1]), "r"(a[2]), "r"(a[3]), "r"(b[0]), "r"(b[1]));
}

// ---------------------------------------------------------------------------
// convw_k: w1x1 fp32 [128][256] -> bf16 hi/lo split (o-major, k-contig)
// ---------------------------------------------------------------------------
__global__ __launch_bounds__(256) void convw_k(const float* __restrict__ w) {
    int i4 = blockIdx.x * 256 + threadIdx.x;           // 8192 quads
    float4 v = *(const float4*)(w + 4 * i4);
    float f[4] = {v.x, v.y, v.z, v.w};
    __nv_bfloat16 hi[4], lo[4];
#pragma unroll
    for (int j = 0; j < 4; j++) {
        hi[j] = __float2bfloat16(f[j]);
        lo[j] = __float2bfloat16(f[j] - __bfloat162float(hi[j]));
    }
    __nv_bfloat162* dh = (__nv_bfloat162*)(g_wh + 4 * i4);
    __nv_bfloat162* dl = (__nv_bfloat162*)(g_wl + 4 * i4);
    dh[0] = __halves2bfloat162(hi[0], hi[1]);
    dh[1] = __halves2bfloat162(hi[2], hi[3]);
    dl[0] = __halves2bfloat162(lo[0], lo[1]);
    dl[1] = __halves2bfloat162(lo[2], lo[3]);
}

// ---------------------------------------------------------------------------
// conv1_mma_k (R11 config): h = conv1x1 via warp-level bf16 mma.sync.
//    D = Ah*Bh + Ah*Bl + Al*Bh   (Al*Bl dropped, ~2^-18 relative)
// ---------------------------------------------------------------------------
static constexpr int SA_H   = 0;            // 128 rows * 528 B
static constexpr int SA_L   = 67584;
static constexpr int SB     = 135168;       // 4 * (32 rows * 272 B) : [buf][hl]
static constexpr int SB_SZ  = 8704;
static constexpr int SM_TOT = 135168 + 4 * SB_SZ;   // 169984 B

__global__ __launch_bounds__(256) void conv1_mma_k(const float* __restrict__ x,
                                                   const float* __restrict__ bias) {
    extern __shared__ char smem[];
    const uint32_t sbase = smem_u32(smem);
    const int tid  = threadIdx.x;
    const int wrp  = tid >> 5;
    const int lane = tid & 31;
    const int b    = blockIdx.y;
    const int p0   = blockIdx.x * 128;

    const int wm = (wrp & 1) * 64;         // warp M offset (o)
    const int wn = (wrp >> 1) * 32;        // warp N offset (px)

    {
        const uint4* sh = (const uint4*)g_wh;
        const uint4* sl = (const uint4*)g_wl;
        for (int u = tid; u < 4096; u += 256) {
            int row = u >> 5, c16 = u & 31;
            *(uint4*)(smem + SA_H + row * 528 + c16 * 16) = sh[u];
            *(uint4*)(smem + SA_L + row * 528 + c16 * 16) = sl[u];
        }
    }

    const float* xb = x + (size_t)b * CIN * PHALF + p0;
    float4 xr[4];
#pragma unroll
    for (int i = 0; i < 4; i++) {
        int u = tid + i * 256;
        int row = u >> 5, seg = u & 31;
        xr[i] = ((const float4*)(xb + (size_t)row * PHALF))[seg];
    }

    float acc[4][4][4];
#pragma unroll
    for (int i = 0; i < 4; i++)
#pragma unroll
        for (int j = 0; j < 4; j++)
#pragma unroll
            for (int q = 0; q < 4; q++) acc[i][j][q] = 0.f;

    for (int kc = 0; kc < 8; kc++) {
        const int buf = kc & 1;
        const uint32_t bh_base = sbase + SB + (buf * 2 + 0) * SB_SZ;
        const uint32_t bl_base = sbase + SB + (buf * 2 + 1) * SB_SZ;

#pragma unroll
        for (int i = 0; i < 4; i++) {
            int u = tid + i * 256;
            int row = u >> 5, seg = u & 31;
            float f[4] = {xr[i].x, xr[i].y, xr[i].z, xr[i].w};
            __nv_bfloat16 hi[4], lo[4];
#pragma unroll
            for (int j = 0; j < 4; j++) {
                hi[j] = __float2bfloat16(f[j]);
                lo[j] = __float2bfloat16(f[j] - __bfloat162float(hi[j]));
            }
            char* ph = smem + SB + (buf * 2 + 0) * SB_SZ + row * 272 + seg * 8;
            char* pl = smem + SB + (buf * 2 + 1) * SB_SZ + row * 272 + seg * 8;
            ((__nv_bfloat162*)ph)[0] = __halves2bfloat162(hi[0], hi[1]);
            ((__nv_bfloat162*)ph)[1] = __halves2bfloat162(hi[2], hi[3]);
            ((__nv_bfloat162*)pl)[0] = __halves2bfloat162(lo[0], lo[1]);
            ((__nv_bfloat162*)pl)[1] = __halves2bfloat162(lo[2], lo[3]);
        }
        __syncthreads();

        if (kc < 7) {
#pragma unroll
            for (int i = 0; i < 4; i++) {
                int u = tid + i * 256;
                int row = u >> 5, seg = u & 31;
                xr[i] = ((const float4*)(xb + (size_t)((kc + 1) * 32 + row) * PHALF))[seg];
            }
        }

#pragma unroll
        for (int s = 0; s < 2; s++) {
            uint32_t a_h[4][4], a_l[4][4];
            const uint32_t akoff = (uint32_t)(kc * 64 + s * 32 + (lane >> 4) * 16);
#pragma unroll
            for (int mt = 0; mt < 4; mt++) {
                uint32_t arow = (uint32_t)(wm + mt * 16 + (lane & 15));
                ldmx4(a_h[mt], sbase + SA_H + arow * 528 + akoff);
                ldmx4(a_l[mt], sbase + SA_L + arow * 528 + akoff);
            }
            uint32_t b_h[4][2], b_l[4][2];
            const uint32_t brow = (uint32_t)(s * 16 + (lane & 15));
#pragma unroll
            for (int nt = 0; nt < 4; nt++) {
                uint32_t bcol = (uint32_t)((wn + nt * 8) * 2);
                ldmx2t(b_h[nt], bh_base + brow * 272 + bcol);
                ldmx2t(b_l[nt], bl_base + brow * 272 + bcol);
            }
#pragma unroll
            for (int mt = 0; mt < 4; mt++)
#pragma unroll
                for (int nt = 0; nt < 4; nt++) {
                    mma_bf16(acc[mt][nt], a_h[mt], b_h[nt]);
                    mma_bf16(acc[mt][nt], a_h[mt], b_l[nt]);
                    mma_bf16(acc[mt][nt], a_l[mt], b_h[nt]);
                }
        }
        __syncthreads();
    }

#pragma unroll
    for (int mt = 0; mt < 4; mt++) {
        int o0 = wm + mt * 16 + (lane >> 2);
        float bv0 = bias[o0];
        float bv1 = bias[o0 + 8];
#pragma unroll
        for (int nt = 0; nt < 4; nt++) {
            int px = p0 + wn + nt * 8 + (lane & 3) * 2;
            float* d0 = g_h + ((size_t)b * COUT + o0) * PHALF + px;
            float* d1 = g_h + ((size_t)b * COUT + o0 + 8) * PHALF + px;
            *(float2*)d0 = make_float2(acc[mt][nt][0] + bv0, acc[mt][nt][1] + bv0);
            *(float2*)d1 = make_float2(acc[mt][nt][2] + bv1, acc[mt][nt][3] + bv1);
        }
    }
}

// ---------------------------------------------------------------------------
// kgen1_k: r = relu(bn(w_red @ h + b_red)) -> g_r.  (stage 1 standalone)
// 64-px blocks, grid 256 (proven R7 structure). Thread = 4o (warp-uniform
// broadcast LDS.128 weights) x 2px. BN+ReLU fused, float2 gmem stores.
// ---------------------------------------------------------------------------
__global__ __launch_bounds__(256) void kgen1_k(const float* __restrict__ wred,
                                               const float* __restrict__ bred,
                                               const float* __restrict__ gamma,
                                               const float* __restrict__ beta,
                                               const float* __restrict__ mean,
                                               const float* __restrict__ var) {
    __shared__ float wredT[CRED * COUT];   // [c][o], 16 KB
    __shared__ float h_sh[16][64];         // h chunk, 4 KB

    const int tid = threadIdx.x;
    const int q0  = blockIdx.x * 64;       // global half-pixel id (b*4096 + p)
    const int b   = q0 >> 12;
    const int p0  = q0 & 4095;

    // wred transposed: wredT[c*32 + o] = wred[o*128 + c]
    for (int i = tid; i < CRED * COUT; i += 256) {
        int o = i >> 7, c = i & 127;
        wredT[c * CRED + o] = wred[i];
    }

    const int oq  = tid >> 5;              // 0..7, warp-uniform
    const int pxp = tid & 31;              // px pair: px = 2*pxp

    float acc[4][2];
#pragma unroll
    for (int i = 0; i < 4; i++) {
        float bv = bred[4 * oq + i];
        acc[i][0] = bv; acc[i][1] = bv;
    }

    const float* hb = g_h + (size_t)b * COUT * PHALF + p0;
    const int hc = tid >> 4, hp4 = tid & 15;   // h loader: one float4 each

    for (int cc = 0; cc < COUT; cc += 16) {
        __syncthreads();
        *(float4*)&h_sh[hc][4 * hp4] =
            *(const float4*)(hb + (size_t)(cc + hc) * PHALF + 4 * hp4);
        __syncthreads();
#pragma unroll
        for (int c = 0; c < 16; c++) {
            float4 wv = *(const float4*)&wredT[(cc + c) * CRED + 4 * oq];  // broadcast
            float2 hv = *(const float2*)&h_sh[c][2 * pxp];
            acc[0][0] += wv.x * hv.x;  acc[0][1] += wv.x * hv.y;
            acc[1][0] += wv.y * hv.x;  acc[1][1] += wv.y * hv.y;
            acc[2][0] += wv.z * hv.x;  acc[2][1] += wv.z * hv.y;
            acc[3][0] += wv.w * hv.x;  acc[3][1] += wv.w * hv.y;
        }
    }

    // BN + ReLU -> gmem
#pragma unroll
    for (int i = 0; i < 4; i++) {
        int o = 4 * oq + i;
        float sc = gamma[o] * rsqrtf(var[o] + 1e-5f);
        float sh = beta[o] - mean[o] * sc;
        float v0 = fmaxf(acc[i][0] * sc + sh, 0.f);
        float v1 = fmaxf(acc[i][1] * sc + sh, 0.f);
        *(float2*)(g_r + ((size_t)b * CRED + o) * PHALF + p0 + 2 * pxp) =
            make_float2(v0, v1);
    }
}

// ---------------------------------------------------------------------------
// kgen2_k: wgt = w_span @ r + b_span   (stage 2 as a clean GEMM)
// 32-px blocks, grid 512, ALL 256 threads active: thread = (sg = tid>>5 owns
// 25 s-rows, lane = px). wspan staged once per block with row pad 36
// (16B-aligned float4 broadcast reads); r tile [32][36].
// Inner: per oo-quad 4 scalar r LDS + 25 broadcast LDS.128 + 100 FMA.
// ---------------------------------------------------------------------------
__global__ __launch_bounds__(256) void kgen2_k(const float* __restrict__ wspan,
                                               const float* __restrict__ bspan) {
    __shared__ float wsp[SPAN * 36];       // [s][oo] pad 36, 28.8 KB
    __shared__ float r_sh[CRED * 36];      // [oo][px] pad 36, 4.6 KB

    const int tid = threadIdx.x;
    const int q0  = blockIdx.x * 32;       // global half-pixel id
    const int b   = q0 >> 12;
    const int p0  = q0 & 4095;

    // stage wspan (row pad 36) and the r tile
    for (int i = tid; i < SPAN * CRED; i += 256) {
        int s = i >> 5, oo = i & 31;
        wsp[s * 36 + oo] = wspan[i];
    }
    for (int i = tid; i < CRED * 32; i += 256) {
        int oo = i >> 5, px = i & 31;
        r_sh[oo * 36 + px] = g_r[((size_t)b * CRED + oo) * PHALF + p0 + px];
    }
    __syncthreads();

    const int sg   = tid >> 5;             // 0..7 -> s rows [sg*25, sg*25+25)
    const int lane = tid & 31;             // px
    const int s_base = sg * 25;

    float acc[KK];
#pragma unroll
    for (int s = 0; s < KK; s++) acc[s] = bspan[s_base + s];

#pragma unroll
    for (int oq = 0; oq < 8; oq++) {       // oo quads
        float rv0 = r_sh[(4 * oq + 0) * 36 + lane];
        float rv1 = r_sh[(4 * oq + 1) * 36 + lane];
        float rv2 = r_sh[(4 * oq + 2) * 36 + lane];
        float rv3 = r_sh[(4 * oq + 3) * 36 + lane];
#pragma unroll
        for (int s = 0; s < KK; s++) {
            float4 w4 = *(const float4*)&wsp[(s_base + s) * 36 + 4 * oq];  // broadcast
            acc[s] += w4.x * rv0 + w4.y * rv1 + w4.z * rv2 + w4.w * rv3;
        }
    }

    float* wb = g_wgt + (size_t)b * SPAN * PHALF + p0 + lane;
#pragma unroll
    for (int s = 0; s < KK; s++)
        wb[(size_t)(s_base + s) * PHALF] = acc[s];   // coalesced per warp
}

// ---------------------------------------------------------------------------
// Kernel 3: involution, pre-collapsed 3x3 weights, 16 channels/block (R11).
// ---------------------------------------------------------------------------
__global__ __launch_bounds__(256) void inv_k(float* __restrict__ out) {
    __shared__ float2 hs[GC_][18][19];   // duplicated halo'd h tile, ~43.8 KB

    const int b = blockIdx.z;
    const int g = blockIdx.y;
    const int ti = (blockIdx.x >> 2) * 16;
    const int tj = (blockIdx.x & 3) * 16;
    const int tid = threadIdx.x;

    const float* hb = g_h + ((size_t)b * COUT + g * GC_) * PHALF;
    for (int e = tid; e < GC_ * 324; e += 256) {
        int c   = e / 324;
        int rem = e - c * 324;
        int rr  = rem / 18, cc = rem - rr * 18;
        int gi = ti - 1 + rr, gj = tj - 1 + cc;
        float v = 0.f;
        if ((unsigned)gi < 64u && (unsigned)gj < 64u)
            v = hb[(size_t)c * PHALF + gi * HHALF + gj];
        hs[c][rr][cc] = make_float2(v, v);
    }

    const int jl = tid & 15, il = tid >> 4;
    const int pix = (ti + il) * HHALF + (tj + jl);

    unsigned long long wA[9], wB[9];     // (W00,W01) and (W10,W11)
    {
        float wk[KK];
        const float* wgp = g_wgt + ((size_t)b * SPAN + g * KK) * PHALF + pix;
#pragma unroll
        for (int k = 0; k < KK; k++) wk[k] = wgp[(size_t)k * PHALF];

        float P0[3][5], P1[3][5];
#pragma unroll
        for (int kw = 0; kw < 5; kw++) {
            P0[0][kw] = wk[0 + kw] + wk[5 + kw];
            P0[1][kw] = wk[10 + kw] + wk[15 + kw];
            P0[2][kw] = wk[20 + kw];
            P1[0][kw] = wk[0 + kw];
            P1[1][kw] = wk[5 + kw] + wk[10 + kw];
            P1[2][kw] = wk[15 + kw] + wk[20 + kw];
        }
#pragma unroll
        for (int r = 0; r < 3; r++) {
            wA[r * 3 + 0] = pk2(P0[r][0] + P0[r][1], P0[r][0]);
            wA[r * 3 + 1] = pk2(P0[r][2] + P0[r][3], P0[r][1] + P0[r][2]);
            wA[r * 3 + 2] = pk2(P0[r][4],            P0[r][3] + P0[r][4]);
            wB[r * 3 + 0] = pk2(P1[r][0] + P1[r][1], P1[r][0]);
            wB[r * 3 + 1] = pk2(P1[r][2] + P1[r][3], P1[r][1] + P1[r][2]);
            wB[r * 3 + 2] = pk2(P1[r][4],            P1[r][3] + P1[r][4]);
        }
    }

    __syncthreads();

    const int y0 = 2 * (ti + il), x0 = 2 * (tj + jl);
    float* ob = out + (((size_t)b * COUT + g * GC_) * 128 + y0) * 128 + x0;

#pragma unroll
    for (int c = 0; c < GC_; c++) {
        unsigned long long m[9];
#pragma unroll
        for (int a = 0; a < 3; a++)
#pragma unroll
            for (int d = 0; d < 3; d++)
                m[a * 3 + d] = *(const unsigned long long*)&hs[c][il + a][jl + d];

        unsigned long long accA = 0ull;  // (a00, a01)
        unsigned long long accB = 0ull;  // (a10, a11)
#pragma unroll
        for (int i = 0; i < 9; i++) {
            fma2(accA, wA[i], m[i]);
            fma2(accB, wB[i], m[i]);
        }
        float a00, a01, a10, a11;
        upk2(accA, a00, a01);
        upk2(accB, a10, a11);
        *reinterpret_cast<float2*>(ob + (size_t)c * 16384)       = make_float2(a00, a01);
        *reinterpret_cast<float2*>(ob + (size_t)c * 16384 + 128) = make_float2(a10, a11);
    }
}

// ---------------------------------------------------------------------------
extern "C" void kernel_launch(void* const* d_in, const int* in_sizes, int n_in,
                              void* d_out, int out_size) {
    const float* x      = (const float*)d_in[0];
    const float* w1x1   = (const float*)d_in[1];
    const float* b1x1   = (const float*)d_in[2];
    const float* w_red  = (const float*)d_in[3];
    const float* b_red  = (const float*)d_in[4];
    const float* gamma  = (const float*)d_in[5];
    const float* beta   = (const float*)d_in[6];
    const float* mean   = (const float*)d_in[7];
    const float* var    = (const float*)d_in[8];
    const float* w_span = (const float*)d_in[9];
    const float* b_span = (const float*)d_in[10];
    float* out = (float*)d_out;

    cudaFuncSetAttribute(conv1_mma_k,
                         cudaFuncAttributeMaxDynamicSharedMemorySize, SM_TOT);

    convw_k<<<32, 256>>>(w1x1);
    conv1_mma_k<<<dim3(PHALF / 128, B_), 256, SM_TOT>>>(x, b1x1);
    kgen1_k<<<dim3((B_ * PHALF) / 64, 1, 1), 256>>>(w_red, b_red, gamma, beta,
                                                    mean, var);
    kgen2_k<<<dim3((B_ * PHALF) / 32, 1, 1), 256>>>(w_span, b_span);
    inv_k<<<dim3(16, GROUPS, B_), 256>>>(out);
}